// round 2
// baseline (speedup 1.0000x reference)
#include <cuda_runtime.h>

// Problem constants
constexpr int cB  = 64;
constexpr int cT  = 512;
constexpr int cIN = 128;
constexpr int cH  = 512;
constexpr int cG  = 4 * cH;   // 2048
constexpr int NB_REC = 128;   // persistent recurrence grid (must be <= SM count)

// ----------------------------------------------------------------------------
// Scratch (device globals; no runtime allocation allowed)
// ----------------------------------------------------------------------------
__device__ float g_xg0[(size_t)cT * cG * cB];   // [t][j][b]  268 MB
__device__ float g_xg1[(size_t)cT * cG * cB];   // [t][j][b]  268 MB
__device__ float g_out0[(size_t)cT * cB * cH];  // [t][b][n]   67 MB (layer-0 h history)
__device__ float g_h1[2 * cB * cH];             // ping-pong [buf][b][n]
__device__ unsigned g_bar_count;
__device__ unsigned g_bar_gen;

__global__ void init_bar_kernel() { g_bar_count = 0u; g_bar_gen = 0u; }

// ----------------------------------------------------------------------------
// Input-projection GEMM:  xg[t][j][b] = (b_ih[j]+b_hh[j]) + sum_k A[b][k] * W[j][k]
//   LAYER 0: A[b][k] = x[(b*T + t)*IN + k],          K = 128
//   LAYER 1: A[b][k] = g_out0[(t*B + b)*H + k],      K = 512
// Block tile: 64 j x 64 b for one t. 256 threads, 4x4 per thread.
// ----------------------------------------------------------------------------
template<int LAYER>
__global__ __launch_bounds__(256) void gemm_xg_kernel(const float* __restrict__ x,
                                                      const float* __restrict__ W,
                                                      const float* __restrict__ bih,
                                                      const float* __restrict__ bhh)
{
    constexpr int K = (LAYER == 0) ? cIN : cH;
    const int t   = blockIdx.y;
    const int j0  = blockIdx.x * 64;
    const int tid = threadIdx.x;
    const int bq  = tid & 15;   // batch quadrant  (16)
    const int jq  = tid >> 4;   // j quadrant      (16)

    // pad 8 floats: row stride 72*4=288 B (16B aligned for float4, 4-way-max banks)
    __shared__ float As[16][72];
    __shared__ float Ws[16][72];

    float acc[4][4];
#pragma unroll
    for (int i = 0; i < 4; i++)
#pragma unroll
        for (int j = 0; j < 4; j++) acc[i][j] = 0.f;

    for (int kt = 0; kt < K; kt += 16) {
#pragma unroll
        for (int r = 0; r < 4; r++) {
            int idx = tid + r * 256;      // 0..1023
            int row = idx >> 4;           // 0..63
            int kk  = idx & 15;
            float av;
            if (LAYER == 0) av = x[((size_t)row * cT + t) * cIN + kt + kk];
            else            av = g_out0[((size_t)t * cB + row) * cH + kt + kk];
            As[kk][row] = av;
            Ws[kk][row] = W[(size_t)(j0 + row) * K + kt + kk];
        }
        __syncthreads();
#pragma unroll
        for (int k = 0; k < 16; k++) {
            float4 a4 = *(const float4*)&As[k][bq * 4];
            float4 w4 = *(const float4*)&Ws[k][jq * 4];
            acc[0][0] += w4.x * a4.x; acc[0][1] += w4.x * a4.y; acc[0][2] += w4.x * a4.z; acc[0][3] += w4.x * a4.w;
            acc[1][0] += w4.y * a4.x; acc[1][1] += w4.y * a4.y; acc[1][2] += w4.y * a4.z; acc[1][3] += w4.y * a4.w;
            acc[2][0] += w4.z * a4.x; acc[2][1] += w4.z * a4.y; acc[2][2] += w4.z * a4.z; acc[2][3] += w4.z * a4.w;
            acc[3][0] += w4.w * a4.x; acc[3][1] += w4.w * a4.y; acc[3][2] += w4.w * a4.z; acc[3][3] += w4.w * a4.w;
        }
        __syncthreads();
    }

    float* xg = (LAYER == 0) ? g_xg0 : g_xg1;
#pragma unroll
    for (int jj = 0; jj < 4; jj++) {
        int j = j0 + jq * 4 + jj;
        float bias = bih[j] + bhh[j];
        float4 v = make_float4(acc[jj][0] + bias, acc[jj][1] + bias,
                               acc[jj][2] + bias, acc[jj][3] + bias);
        *(float4*)&xg[((size_t)t * cG + j) * cB + bq * 4] = v;
    }
}

// ----------------------------------------------------------------------------
// Persistent LSTM recurrence.
// 128 blocks x 256 threads. Block bid owns h-indices n in [4*bid, 4*bid+4).
// Thread (b = tid&63, nq = tid>>6) owns one (batch, n) pair: computes all 4
// gate dot-products (K=512) per step, keeps c in a register across all T.
// W_hh slice (16 rows) lives in SMEM for the whole kernel.
// Grid-wide sync via monotonic-generation software barrier.
// ----------------------------------------------------------------------------
template<int LAYER>
__global__ __launch_bounds__(256) void lstm_rec_kernel(const float* __restrict__ Whh)
{
    const int tid = threadIdx.x;
    const int b   = tid & 63;
    const int nq  = tid >> 6;           // 0..3
    const int bid = blockIdx.x;
    const int n   = bid * 4 + nq;       // 0..511

    __shared__ float Ws[16][cH];        // [gate*4 + q][k], 32 KB

    for (int idx = tid; idx < 16 * cH; idx += 256) {
        int r = idx >> 9;               // 0..15
        int k = idx & 511;
        int j = (r >> 2) * cH + bid * 4 + (r & 3);
        Ws[r][k] = Whh[(size_t)j * cH + k];
    }
    __syncthreads();

    // All lanes of a warp share nq -> these SMEM reads are pure broadcast.
    const float4* wi = (const float4*)Ws[0 * 4 + nq];
    const float4* wf = (const float4*)Ws[1 * 4 + nq];
    const float4* wg = (const float4*)Ws[2 * 4 + nq];
    const float4* wo = (const float4*)Ws[3 * 4 + nq];

    const float* xg = (LAYER == 0) ? g_xg0 : g_xg1;

    float c = 0.f;
    unsigned gen = 0;

    for (int t = 0; t < cT; t++) {
        const float* xgt = xg + (size_t)t * cG * cB;
        float ai = xgt[(0 * cH + n) * cB + b];
        float af = xgt[(1 * cH + n) * cB + b];
        float ag = xgt[(2 * cH + n) * cB + b];
        float ao = xgt[(3 * cH + n) * cB + b];

        if (t > 0) {
            const float* hprev = (LAYER == 0)
                ? (g_out0 + (size_t)(t - 1) * cB * cH)
                : (g_h1   + (size_t)(t & 1) * cB * cH);
            const float4* hp = (const float4*)(hprev + (size_t)b * cH);
#pragma unroll 4
            for (int k4 = 0; k4 < cH / 4; k4++) {
                float4 h4 = hp[k4];
                float4 w;
                w = wi[k4]; ai += w.x * h4.x + w.y * h4.y + w.z * h4.z + w.w * h4.w;
                w = wf[k4]; af += w.x * h4.x + w.y * h4.y + w.z * h4.z + w.w * h4.w;
                w = wg[k4]; ag += w.x * h4.x + w.y * h4.y + w.z * h4.z + w.w * h4.w;
                w = wo[k4]; ao += w.x * h4.x + w.y * h4.y + w.z * h4.z + w.w * h4.w;
            }
        }

        float iv = 1.f / (1.f + expf(-ai));
        float fv = 1.f / (1.f + expf(-af));
        float gv = tanhf(ag);
        float ov = 1.f / (1.f + expf(-ao));
        c = fv * c + iv * gv;
        float h = ov * tanhf(c);

        float* hout = (LAYER == 0)
            ? (g_out0 + (size_t)t * cB * cH)
            : (g_h1   + (size_t)((t + 1) & 1) * cB * cH);
        hout[(size_t)b * cH + n] = h;

        // ---- grid barrier (monotonic generation; no counter reset races) ----
        __syncthreads();
        if (tid == 0) {
            __threadfence();
            unsigned arr = atomicAdd(&g_bar_count, 1u) + 1u;
            unsigned target = gen + 1u;
            if (arr == (unsigned)NB_REC * target) {
                atomicExch(&g_bar_gen, target);
            } else {
                while (*((volatile unsigned*)&g_bar_gen) < target) { }
            }
            __threadfence();
        }
        gen++;
        __syncthreads();
    }
}

// ----------------------------------------------------------------------------
// Final FC on last timestep of layer-1 h (lives in g_h1 buffer 0: (511+1)&1 == 0)
// ----------------------------------------------------------------------------
__global__ __launch_bounds__(128) void fc_kernel(const float* __restrict__ Wfc,
                                                 const float* __restrict__ bfc,
                                                 float* __restrict__ out)
{
    int b   = blockIdx.x;
    int tid = threadIdx.x;    // 128
    const float* h = g_h1 + (size_t)b * cH;
    float s = 0.f;
    for (int k = tid; k < cH; k += 128) s += h[k] * Wfc[k];
    __shared__ float red[128];
    red[tid] = s;
    __syncthreads();
    for (int o = 64; o > 0; o >>= 1) {
        if (tid < o) red[tid] += red[tid + o];
        __syncthreads();
    }
    if (tid == 0) out[b] = red[0] + bfc[0];
}

// ----------------------------------------------------------------------------
extern "C" void kernel_launch(void* const* d_in, const int* in_sizes, int n_in,
                              void* d_out, int out_size)
{
    const float* x     = (const float*)d_in[0];
    const float* W_ih0 = (const float*)d_in[1];
    const float* W_hh0 = (const float*)d_in[2];
    const float* b_ih0 = (const float*)d_in[3];
    const float* b_hh0 = (const float*)d_in[4];
    const float* W_ih1 = (const float*)d_in[5];
    const float* W_hh1 = (const float*)d_in[6];
    const float* b_ih1 = (const float*)d_in[7];
    const float* b_hh1 = (const float*)d_in[8];
    const float* W_fc  = (const float*)d_in[9];
    const float* b_fc  = (const float*)d_in[10];
    float* out = (float*)d_out;
    (void)in_sizes; (void)n_in; (void)out_size;

    dim3 ggrid(cG / 64, cT);
    gemm_xg_kernel<0><<<ggrid, 256>>>(x, W_ih0, b_ih0, b_hh0);
    init_bar_kernel<<<1, 1>>>();
    lstm_rec_kernel<0><<<NB_REC, 256>>>(W_hh0);
    gemm_xg_kernel<1><<<ggrid, 256>>>(nullptr, W_ih1, b_ih1, b_hh1);
    init_bar_kernel<<<1, 1>>>();
    lstm_rec_kernel<1><<<NB_REC, 256>>>(W_hh1);
    fc_kernel<<<cB, 128>>>(W_fc, b_fc, out);
}

// round 6
// speedup vs baseline: 1.7740x; 1.7740x over previous
#include <cuda_runtime.h>

// Problem constants
constexpr int cB  = 64;
constexpr int cT  = 512;
constexpr int cIN = 128;
constexpr int cH  = 512;
constexpr int cG  = 4 * cH;   // 2048
constexpr int NB_REC = 128;   // persistent recurrence grid (<= SM count)

constexpr int HS_PAD  = 516;  // hs row stride in floats (conflict-free LDS.128)
constexpr int REC_SMEM = (16 * cH + cB * HS_PAD) * 4;  // 32KB weights + 129KB h stage

// ----------------------------------------------------------------------------
// Scratch (device globals; no runtime allocation allowed)
// ----------------------------------------------------------------------------
__device__ float g_xg0[(size_t)cT * cG * cB];   // [t][j][b]
__device__ float g_xg1[(size_t)cT * cG * cB];   // [t][j][b]
__device__ float g_out0[(size_t)cT * cB * cH];  // [t][b][n] layer-0 h history
__device__ float g_h1[2 * cB * cH];             // ping-pong [buf][b][n]
__device__ unsigned g_bar_count;
__device__ unsigned g_bar_gen;

__global__ void init_bar_kernel() { g_bar_count = 0u; g_bar_gen = 0u; }

// ----------------------------------------------------------------------------
// helpers
// ----------------------------------------------------------------------------
__device__ __forceinline__ unsigned long long ffma2(unsigned long long a,
                                                    unsigned long long b,
                                                    unsigned long long c) {
    unsigned long long d;
    asm("fma.rn.f32x2 %0, %1, %2, %3;" : "=l"(d) : "l"(a), "l"(b), "l"(c));
    return d;
}
__device__ __forceinline__ unsigned long long packff(float v) {
    unsigned u = __float_as_uint(v);
    return (unsigned long long)u | ((unsigned long long)u << 32);
}
__device__ __forceinline__ float f2lo(unsigned long long p) {
    return __uint_as_float((unsigned)(p & 0xffffffffull));
}
__device__ __forceinline__ float f2hi(unsigned long long p) {
    return __uint_as_float((unsigned)(p >> 32));
}
__device__ __forceinline__ void cp16(void* dst, const void* src) {
    unsigned d = (unsigned)__cvta_generic_to_shared(dst);
    asm volatile("cp.async.cg.shared.global [%0], [%1], 16;" :: "r"(d), "l"(src));
}
__device__ __forceinline__ void cp_commit() {
    asm volatile("cp.async.commit_group;");
}
template<int N>
__device__ __forceinline__ void cp_wait() {
    asm volatile("cp.async.wait_group %0;" :: "n"(N));
}

// ----------------------------------------------------------------------------
// Input-projection GEMM (f32x2 packed, double-buffered):
//   xg[t][j][b] = (b_ih[j]+b_hh[j]) + sum_k A[b][k] * W[j][k]
//   LAYER 0: A[b][k] = x[(b*T + t)*IN + k],     K = 128
//   LAYER 1: A[b][k] = g_out0[(t*B + b)*H + k], K = 512
// Tile 64 j x 64 b per t. 256 threads: bq=tid&15 (4 batches = 2 pairs),
// jq=tid>>4 (4 j rows). 8 packed accumulators per thread.
// ----------------------------------------------------------------------------
template<int LAYER>
__global__ __launch_bounds__(256) void gemm_xg_kernel(const float* __restrict__ x,
                                                      const float* __restrict__ W,
                                                      const float* __restrict__ bih,
                                                      const float* __restrict__ bhh)
{
    constexpr int K = (LAYER == 0) ? cIN : cH;
    constexpr int ITERS = K / 16;
    const int t   = blockIdx.y;
    const int j0  = blockIdx.x * 64;
    const int tid = threadIdx.x;
    const int bq  = tid & 15;
    const int jq  = tid >> 4;

    __shared__ float              As[2][16][72];           // [k][b], pad 8
    __shared__ unsigned long long Wsp[2][16][68];          // packed (w,w), pad 4

    unsigned long long acc[4][2];
#pragma unroll
    for (int j = 0; j < 4; j++) { acc[j][0] = 0ull; acc[j][1] = 0ull; }

    float av[4], wv[4];

    // prologue: tile 0
#pragma unroll
    for (int r = 0; r < 4; r++) {
        int idx = tid + r * 256;
        int row = idx >> 4, kk = idx & 15;
        if (LAYER == 0) av[r] = x[((size_t)row * cT + t) * cIN + kk];
        else            av[r] = g_out0[((size_t)t * cB + row) * cH + kk];
        wv[r] = W[(size_t)(j0 + row) * K + kk];
    }
#pragma unroll
    for (int r = 0; r < 4; r++) {
        int idx = tid + r * 256;
        int row = idx >> 4, kk = idx & 15;
        As[0][kk][row]  = av[r];
        Wsp[0][kk][row] = packff(wv[r]);
    }
    __syncthreads();

    for (int it = 0; it < ITERS; it++) {
        const int buf = it & 1;
        const bool more = (it + 1 < ITERS);
        if (more) {
            int kt = (it + 1) * 16;
#pragma unroll
            for (int r = 0; r < 4; r++) {
                int idx = tid + r * 256;
                int row = idx >> 4, kk = idx & 15;
                if (LAYER == 0) av[r] = x[((size_t)row * cT + t) * cIN + kt + kk];
                else            av[r] = g_out0[((size_t)t * cB + row) * cH + kt + kk];
                wv[r] = W[(size_t)(j0 + row) * K + kt + kk];
            }
        }
#pragma unroll
        for (int k = 0; k < 16; k++) {
            const ulonglong2 a2 = *(const ulonglong2*)&As[buf][k][bq * 4];
            const ulonglong2 w01 = *(const ulonglong2*)&Wsp[buf][k][jq * 4];
            const ulonglong2 w23 = *(const ulonglong2*)&Wsp[buf][k][jq * 4 + 2];
            acc[0][0] = ffma2(w01.x, a2.x, acc[0][0]);
            acc[0][1] = ffma2(w01.x, a2.y, acc[0][1]);
            acc[1][0] = ffma2(w01.y, a2.x, acc[1][0]);
            acc[1][1] = ffma2(w01.y, a2.y, acc[1][1]);
            acc[2][0] = ffma2(w23.x, a2.x, acc[2][0]);
            acc[2][1] = ffma2(w23.x, a2.y, acc[2][1]);
            acc[3][0] = ffma2(w23.y, a2.x, acc[3][0]);
            acc[3][1] = ffma2(w23.y, a2.y, acc[3][1]);
        }
        if (more) {
            __syncthreads();
#pragma unroll
            for (int r = 0; r < 4; r++) {
                int idx = tid + r * 256;
                int row = idx >> 4, kk = idx & 15;
                As[buf ^ 1][kk][row]  = av[r];
                Wsp[buf ^ 1][kk][row] = packff(wv[r]);
            }
            __syncthreads();
        }
    }

    float* xg = (LAYER == 0) ? g_xg0 : g_xg1;
#pragma unroll
    for (int jj = 0; jj < 4; jj++) {
        int j = j0 + jq * 4 + jj;
        float bias = bih[j] + bhh[j];
        float4 v = make_float4(f2lo(acc[jj][0]) + bias, f2hi(acc[jj][0]) + bias,
                               f2lo(acc[jj][1]) + bias, f2hi(acc[jj][1]) + bias);
        *(float4*)&xg[((size_t)t * cG + j) * cB + bq * 4] = v;
    }
}

// ----------------------------------------------------------------------------
// Persistent LSTM recurrence with SMEM-staged h.
// 128 blocks x 256 threads; block owns n in [4*bid, 4*bid+4).
// Thread (b=tid&63, nq=tid>>6) computes all 4 gates for (b, n); c in register.
// Per step, hprev (128KB) is staged into SMEM via cp.async.cg (L1-bypass,
// fixes cross-SM coherence) in 2 K-chunks overlapping the first compute half.
// ----------------------------------------------------------------------------
template<int LAYER>
__global__ __launch_bounds__(256, 1) void lstm_rec_kernel(const float* __restrict__ Whh)
{
    extern __shared__ float sm[];
    float* ws = sm;               // [16][cH]
    float* hs = sm + 16 * cH;     // [cB][HS_PAD]

    const int tid = threadIdx.x;
    const int b   = tid & 63;
    const int nq  = tid >> 6;
    const int bid = blockIdx.x;

    for (int idx = tid; idx < 16 * cH; idx += 256) {
        int r = idx >> 9;
        int k = idx & 511;
        int j = (r >> 2) * cH + bid * 4 + (r & 3);
        ws[r * cH + k] = Whh[(size_t)j * cH + k];
    }
    __syncthreads();

    const float4* wi = (const float4*)(ws + (0 * 4 + nq) * cH);
    const float4* wf = (const float4*)(ws + (1 * 4 + nq) * cH);
    const float4* wg = (const float4*)(ws + (2 * 4 + nq) * cH);
    const float4* wo = (const float4*)(ws + (3 * 4 + nq) * cH);
    const float4* hp = (const float4*)(hs + b * HS_PAD);

    const float* xg = (LAYER == 0) ? g_xg0 : g_xg1;
    const int n = bid * 4 + nq;

    float c = 0.f;
    unsigned gen = 0;

    for (int t = 0; t < cT; t++) {
        // stage hprev -> SMEM, 2 chunks of K=256 each (cp.async.cg)
        if (t > 0) {
            const float* hprev = (LAYER == 0)
                ? (g_out0 + (size_t)(t - 1) * cB * cH)
                : (g_h1   + (size_t)(t & 1) * cB * cH);
#pragma unroll
            for (int ch = 0; ch < 2; ch++) {
                for (int i = tid; i < 4096; i += 256) {
                    int b2 = i >> 6;
                    int kq = i & 63;
                    cp16(hs + b2 * HS_PAD + ch * 256 + kq * 4,
                         hprev + b2 * cH + ch * 256 + kq * 4);
                }
                cp_commit();
            }
        }

        const float* xgt = xg + (size_t)t * cG * cB;
        float ai = xgt[(0 * cH + n) * cB + b];
        float af = xgt[(1 * cH + n) * cB + b];
        float ag = xgt[(2 * cH + n) * cB + b];
        float ao = xgt[(3 * cH + n) * cB + b];

        if (t > 0) {
            cp_wait<1>();
            __syncthreads();
#pragma unroll 4
            for (int k4 = 0; k4 < 64; k4++) {
                float4 h4 = hp[k4];
                float4 w;
                w = wi[k4]; ai += w.x * h4.x + w.y * h4.y + w.z * h4.z + w.w * h4.w;
                w = wf[k4]; af += w.x * h4.x + w.y * h4.y + w.z * h4.z + w.w * h4.w;
                w = wg[k4]; ag += w.x * h4.x + w.y * h4.y + w.z * h4.z + w.w * h4.w;
                w = wo[k4]; ao += w.x * h4.x + w.y * h4.y + w.z * h4.z + w.w * h4.w;
            }
            cp_wait<0>();
            __syncthreads();
#pragma unroll 4
            for (int k4 = 64; k4 < 128; k4++) {
                float4 h4 = hp[k4];
                float4 w;
                w = wi[k4]; ai += w.x * h4.x + w.y * h4.y + w.z * h4.z + w.w * h4.w;
                w = wf[k4]; af += w.x * h4.x + w.y * h4.y + w.z * h4.z + w.w * h4.w;
                w = wg[k4]; ag += w.x * h4.x + w.y * h4.y + w.z * h4.z + w.w * h4.w;
                w = wo[k4]; ao += w.x * h4.x + w.y * h4.y + w.z * h4.z + w.w * h4.w;
            }
        }

        float iv = 1.f / (1.f + expf(-ai));
        float fv = 1.f / (1.f + expf(-af));
        float gv = tanhf(ag);
        float ov = 1.f / (1.f + expf(-ao));
        c = fv * c + iv * gv;
        float h = ov * tanhf(c);

        float* hout = (LAYER == 0)
            ? (g_out0 + (size_t)t * cB * cH)
            : (g_h1   + (size_t)((t + 1) & 1) * cB * cH);
        hout[(size_t)b * cH + n] = h;

        // grid barrier (monotonic generation)
        __syncthreads();
        if (tid == 0) {
            __threadfence();
            unsigned arr = atomicAdd(&g_bar_count, 1u) + 1u;
            unsigned target = gen + 1u;
            if (arr == (unsigned)NB_REC * target) {
                atomicExch(&g_bar_gen, target);
            } else {
                while (*((volatile unsigned*)&g_bar_gen) < target) { }
            }
            __threadfence();
        }
        gen++;
        __syncthreads();
    }
}

// ----------------------------------------------------------------------------
// Final FC on last h of layer 1 (lives in g_h1 buffer 0)
// ----------------------------------------------------------------------------
__global__ __launch_bounds__(128) void fc_kernel(const float* __restrict__ Wfc,
                                                 const float* __restrict__ bfc,
                                                 float* __restrict__ out)
{
    int b   = blockIdx.x;
    int tid = threadIdx.x;
    const float* h = g_h1 + (size_t)b * cH;
    float s = 0.f;
    for (int k = tid; k < cH; k += 128) s += h[k] * Wfc[k];
    __shared__ float red[128];
    red[tid] = s;
    __syncthreads();
    for (int o = 64; o > 0; o >>= 1) {
        if (tid < o) red[tid] += red[tid + o];
        __syncthreads();
    }
    if (tid == 0) out[b] = red[0] + bfc[0];
}

// ----------------------------------------------------------------------------
extern "C" void kernel_launch(void* const* d_in, const int* in_sizes, int n_in,
                              void* d_out, int out_size)
{
    const float* x     = (const float*)d_in[0];
    const float* W_ih0 = (const float*)d_in[1];
    const float* W_hh0 = (const float*)d_in[2];
    const float* b_ih0 = (const float*)d_in[3];
    const float* b_hh0 = (const float*)d_in[4];
    const float* W_ih1 = (const float*)d_in[5];
    const float* W_hh1 = (const float*)d_in[6];
    const float* b_ih1 = (const float*)d_in[7];
    const float* b_hh1 = (const float*)d_in[8];
    const float* W_fc  = (const float*)d_in[9];
    const float* b_fc  = (const float*)d_in[10];
    float* out = (float*)d_out;
    (void)in_sizes; (void)n_in; (void)out_size;

    cudaFuncSetAttribute(lstm_rec_kernel<0>,
                         cudaFuncAttributeMaxDynamicSharedMemorySize, REC_SMEM);
    cudaFuncSetAttribute(lstm_rec_kernel<1>,
                         cudaFuncAttributeMaxDynamicSharedMemorySize, REC_SMEM);

    dim3 ggrid(cG / 64, cT);
    gemm_xg_kernel<0><<<ggrid, 256>>>(x, W_ih0, b_ih0, b_hh0);
    init_bar_kernel<<<1, 1>>>();
    lstm_rec_kernel<0><<<NB_REC, 256, REC_SMEM>>>(W_hh0);
    gemm_xg_kernel<1><<<ggrid, 256>>>(nullptr, W_ih1, b_ih1, b_hh1);
    init_bar_kernel<<<1, 1>>>();
    lstm_rec_kernel<1><<<NB_REC, 256, REC_SMEM>>>(W_hh1);
    fc_kernel<<<cB, 128>>>(W_fc, b_fc, out);
}

// round 8
// speedup vs baseline: 2.0305x; 1.1446x over previous
#include <cuda_runtime.h>

// Problem constants
constexpr int cB  = 64;
constexpr int cT  = 512;
constexpr int cIN = 128;
constexpr int cH  = 512;
constexpr int cG  = 4 * cH;   // 2048
constexpr int NB_REC = 128;   // persistent recurrence grid (<= SM count)

constexpr int HS_PAD = 516;   // hs row stride (floats): conflict-free h loads
constexpr int WS_PAD = 520;   // ws row stride (floats): n-rows on distinct banks
constexpr int REC_SMEM  = (16 * WS_PAD + cB * HS_PAD) * 4;          // 165,376 B
constexpr int GEMM_SMEM = 2 * 32 * 68 * 4 + 2 * 32 * 66 * 8;        // 51,200 B

// ----------------------------------------------------------------------------
// Scratch (device globals; no runtime allocation allowed)
// ----------------------------------------------------------------------------
__device__ float g_xg0[(size_t)cT * cG * cB];    // [t][j][b]
__device__ float g_xg1[(size_t)cT * cG * cB];    // [t][j][b]
__device__ float g_out0[(size_t)cT * cB * cH];   // [t][b][n]  (staging source)
__device__ float g_out0T[(size_t)cT * cH * cB];  // [t][n][b]  (GEMM1 A source)
__device__ float g_xT[(size_t)cT * cIN * cB];    // [t][k][b]  (GEMM0 A source)
__device__ unsigned long long g_Wp0[(size_t)cIN * cG];  // packed (w,w) [k][j]
__device__ unsigned long long g_Wp1[(size_t)cH * cG];   // packed (w,w) [k][j]
__device__ float g_h1[2 * cB * cH];              // ping-pong [buf][b][n]
__device__ unsigned g_bar_count;
__device__ unsigned g_bar_gen;

__global__ void init_bar_kernel() { g_bar_count = 0u; g_bar_gen = 0u; }

// ----------------------------------------------------------------------------
// helpers
// ----------------------------------------------------------------------------
__device__ __forceinline__ unsigned long long ffma2(unsigned long long a,
                                                    unsigned long long b,
                                                    unsigned long long c) {
    unsigned long long d;
    asm("fma.rn.f32x2 %0, %1, %2, %3;" : "=l"(d) : "l"(a), "l"(b), "l"(c));
    return d;
}
__device__ __forceinline__ unsigned long long packff(float v) {
    unsigned u = __float_as_uint(v);
    return (unsigned long long)u | ((unsigned long long)u << 32);
}
__device__ __forceinline__ float f2lo(unsigned long long p) {
    return __uint_as_float((unsigned)(p & 0xffffffffull));
}
__device__ __forceinline__ float f2hi(unsigned long long p) {
    return __uint_as_float((unsigned)(p >> 32));
}
__device__ __forceinline__ void cp16(void* dst, const void* src) {
    unsigned d = (unsigned)__cvta_generic_to_shared(dst);
    asm volatile("cp.async.cg.shared.global [%0], [%1], 16;" :: "r"(d), "l"(src));
}
__device__ __forceinline__ void cp_commit() {
    asm volatile("cp.async.commit_group;");
}
template<int N>
__device__ __forceinline__ void cp_wait() {
    asm volatile("cp.async.wait_group %0;" :: "n"(N));
}

// ----------------------------------------------------------------------------
// Prep: transpose x[b][t][k] -> g_xT[t][k][b]
// ----------------------------------------------------------------------------
__global__ __launch_bounds__(256) void transpose_x_kernel(const float* __restrict__ x)
{
    __shared__ float sm[cIN][65];
    const int t = blockIdx.x, tid = threadIdx.x;
    for (int i = tid; i < cB * cIN; i += 256) {
        int b = i >> 7, k = i & 127;
        sm[k][b] = x[((size_t)b * cT + t) * cIN + k];
    }
    __syncthreads();
    for (int i = tid; i < cIN * cB; i += 256) {
        int k = i >> 6, b = i & 63;
        g_xT[((size_t)t * cIN + k) * cB + b] = sm[k][b];
    }
}

// ----------------------------------------------------------------------------
// Prep: pack W_ih[j][k] -> Wp[k][j] with (w,w) duplication
// ----------------------------------------------------------------------------
template<int LAYER>
__global__ __launch_bounds__(256) void pack_w_kernel(const float* __restrict__ W)
{
    constexpr int K = (LAYER == 0) ? cIN : cH;
    const int k = blockIdx.x;
    unsigned long long* Wp = (LAYER == 0) ? g_Wp0 : g_Wp1;
    for (int j = threadIdx.x; j < cG; j += 256)
        Wp[(size_t)k * cG + j] = packff(W[(size_t)j * K + k]);
}

// ----------------------------------------------------------------------------
// Input-projection GEMM, cp.async double-buffered, f32x2, K-tile 32.
//   xg[t][j][b] = (b_ih[j]+b_hh[j]) + sum_k A[t][k][b] * W[j][k]
// Tile 64 j x 64 b per t. 256 threads: bq=tid&15 (batch quad), jq=tid>>4.
// ----------------------------------------------------------------------------
template<int LAYER>
__global__ __launch_bounds__(256) void gemm_xg_kernel(const float* __restrict__ bih,
                                                      const float* __restrict__ bhh)
{
    constexpr int K  = (LAYER == 0) ? cIN : cH;
    constexpr int NT = K / 32;
    const int t   = blockIdx.y;
    const int j0  = blockIdx.x * 64;
    const int tid = threadIdx.x;
    const int bq  = tid & 15;
    const int jq  = tid >> 4;

    extern __shared__ char smraw[];
    float* As               = (float*)smraw;                      // [2][32][68]
    unsigned long long* Wsp = (unsigned long long*)(smraw + 2 * 32 * 68 * 4);  // [2][32][66]

    const float* aT = (LAYER == 0) ? g_xT : g_out0T;
    const unsigned long long* Wp = (LAYER == 0) ? g_Wp0 : g_Wp1;

    auto issue_tile = [&](int it, int buf) {
        const int kt = it * 32;
        // A: 32 rows x 64 floats = 512 x 16B chunks
#pragma unroll
        for (int r = 0; r < 2; r++) {
            int c = tid + r * 256;
            int k = c >> 4, b4 = (c & 15) * 4;
            cp16(As + ((size_t)buf * 32 + k) * 68 + b4,
                 aT + ((size_t)t * K + kt + k) * cB + b4);
        }
        // W: 32 rows x 64 ull = 1024 x 16B chunks
#pragma unroll
        for (int r = 0; r < 4; r++) {
            int c = tid + r * 256;
            int k = c >> 5, j2 = (c & 31) * 2;
            cp16(Wsp + ((size_t)buf * 32 + k) * 66 + j2,
                 Wp + (size_t)(kt + k) * cG + j0 + j2);
        }
        cp_commit();
    };

    unsigned long long acc[4][2];
#pragma unroll
    for (int j = 0; j < 4; j++) { acc[j][0] = 0ull; acc[j][1] = 0ull; }

    issue_tile(0, 0);
    for (int it = 0; it < NT; it++) {
        const int buf = it & 1;
        if (it + 1 < NT) { issue_tile(it + 1, buf ^ 1); cp_wait<1>(); }
        else             { cp_wait<0>(); }
        __syncthreads();
        const float* Ab = As + (size_t)buf * 32 * 68;
        const unsigned long long* Wb = Wsp + (size_t)buf * 32 * 66;
#pragma unroll 16
        for (int k = 0; k < 32; k++) {
            const ulonglong2 a2  = *(const ulonglong2*)(Ab + k * 68 + bq * 4);
            const ulonglong2 w01 = *(const ulonglong2*)(Wb + k * 66 + jq * 4);
            const ulonglong2 w23 = *(const ulonglong2*)(Wb + k * 66 + jq * 4 + 2);
            acc[0][0] = ffma2(w01.x, a2.x, acc[0][0]);
            acc[0][1] = ffma2(w01.x, a2.y, acc[0][1]);
            acc[1][0] = ffma2(w01.y, a2.x, acc[1][0]);
            acc[1][1] = ffma2(w01.y, a2.y, acc[1][1]);
            acc[2][0] = ffma2(w23.x, a2.x, acc[2][0]);
            acc[2][1] = ffma2(w23.x, a2.y, acc[2][1]);
            acc[3][0] = ffma2(w23.y, a2.x, acc[3][0]);
            acc[3][1] = ffma2(w23.y, a2.y, acc[3][1]);
        }
        __syncthreads();
    }

    float* xg = (LAYER == 0) ? g_xg0 : g_xg1;
#pragma unroll
    for (int jj = 0; jj < 4; jj++) {
        int j = j0 + jq * 4 + jj;
        float bias = bih[j] + bhh[j];
        float4 v = make_float4(f2lo(acc[jj][0]) + bias, f2hi(acc[jj][0]) + bias,
                               f2lo(acc[jj][1]) + bias, f2hi(acc[jj][1]) + bias);
        *(float4*)&xg[((size_t)t * cG + j) * cB + bq * 4] = v;
    }
}

// ----------------------------------------------------------------------------
// Persistent LSTM recurrence, v2.
// 128 blocks x 256 threads; block owns n in [4*bid, 4*bid+4).
// Lane map: warp w covers b in [8w, 8w+8) x 4 n (lane = nq*8 + b_lo):
//   h loads  : 8 distinct 16B rows/warp = 1 crossbar phase (was 4)
//   w loads  : 4 distinct rows x 8-lane broadcast = 1 phase each
// Dot products in f32x2 (packed k-pairs). xg for t+1 prefetched early.
// ----------------------------------------------------------------------------
template<int LAYER>
__global__ __launch_bounds__(256, 1) void lstm_rec_kernel(const float* __restrict__ Whh)
{
    extern __shared__ float sm[];
    float* ws = sm;                        // [16][WS_PAD]
    float* hs = sm + 16 * WS_PAD;          // [cB][HS_PAD]

    const int tid  = threadIdx.x;
    const int wrp  = tid >> 5;
    const int lane = tid & 31;
    const int b    = wrp * 8 + (lane & 7);
    const int nq   = lane >> 3;            // 0..3
    const int bid  = blockIdx.x;
    const int n    = bid * 4 + nq;

    for (int idx = tid; idx < 16 * cH; idx += 256) {
        int r = idx >> 9, k = idx & 511;
        ws[r * WS_PAD + k] = Whh[(size_t)((r >> 2) * cH + bid * 4 + (r & 3)) * cH + k];
    }
    __syncthreads();

    const ulonglong2* wi = (const ulonglong2*)(ws + (0 * 4 + nq) * WS_PAD);
    const ulonglong2* wf = (const ulonglong2*)(ws + (1 * 4 + nq) * WS_PAD);
    const ulonglong2* wg = (const ulonglong2*)(ws + (2 * 4 + nq) * WS_PAD);
    const ulonglong2* wo = (const ulonglong2*)(ws + (3 * 4 + nq) * WS_PAD);
    const ulonglong2* hp = (const ulonglong2*)(hs + b * HS_PAD);

    const float* xg = (LAYER == 0) ? g_xg0 : g_xg1;

    float c = 0.f;
    unsigned gen = 0;

    // prefetch xg for t=0
    float nai = xg[(0 * cH + n) * cB + b];
    float naf = xg[(1 * cH + n) * cB + b];
    float nag = xg[(2 * cH + n) * cB + b];
    float nao = xg[(3 * cH + n) * cB + b];

    for (int t = 0; t < cT; t++) {
        float ai = nai, af = naf, ag = nag, ao = nao;

        // stage hprev -> SMEM (cp.async.cg, 2 chunks), overlapped with compute
        if (t > 0) {
            const float* hprev = (LAYER == 0)
                ? (g_out0 + (size_t)(t - 1) * cB * cH)
                : (g_h1   + (size_t)(t & 1) * cB * cH);
#pragma unroll
            for (int ch = 0; ch < 2; ch++) {
                for (int i = tid; i < 4096; i += 256) {
                    int b2 = i >> 6, kq = i & 63;
                    cp16(hs + b2 * HS_PAD + ch * 256 + kq * 4,
                         hprev + b2 * cH + ch * 256 + kq * 4);
                }
                cp_commit();
            }
        }

        // prefetch xg for t+1 (hides DRAM latency behind the dot product)
        if (t + 1 < cT) {
            const float* xn = xg + (size_t)(t + 1) * cG * cB;
            nai = xn[(0 * cH + n) * cB + b];
            naf = xn[(1 * cH + n) * cB + b];
            nag = xn[(2 * cH + n) * cB + b];
            nao = xn[(3 * cH + n) * cB + b];
        }

        if (t > 0) {
            unsigned long long pi = 0ull, pf = 0ull, pg = 0ull, po = 0ull;
            cp_wait<1>();
            __syncthreads();
#pragma unroll 8
            for (int k4 = 0; k4 < 64; k4++) {
                ulonglong2 h2 = hp[k4];
                ulonglong2 wv;
                wv = wi[k4]; pi = ffma2(wv.x, h2.x, pi); pi = ffma2(wv.y, h2.y, pi);
                wv = wf[k4]; pf = ffma2(wv.x, h2.x, pf); pf = ffma2(wv.y, h2.y, pf);
                wv = wg[k4]; pg = ffma2(wv.x, h2.x, pg); pg = ffma2(wv.y, h2.y, pg);
                wv = wo[k4]; po = ffma2(wv.x, h2.x, po); po = ffma2(wv.y, h2.y, po);
            }
            cp_wait<0>();
            __syncthreads();
#pragma unroll 8
            for (int k4 = 64; k4 < 128; k4++) {
                ulonglong2 h2 = hp[k4];
                ulonglong2 wv;
                wv = wi[k4]; pi = ffma2(wv.x, h2.x, pi); pi = ffma2(wv.y, h2.y, pi);
                wv = wf[k4]; pf = ffma2(wv.x, h2.x, pf); pf = ffma2(wv.y, h2.y, pf);
                wv = wg[k4]; pg = ffma2(wv.x, h2.x, pg); pg = ffma2(wv.y, h2.y, pg);
                wv = wo[k4]; po = ffma2(wv.x, h2.x, po); po = ffma2(wv.y, h2.y, po);
            }
            ai += f2lo(pi) + f2hi(pi);
            af += f2lo(pf) + f2hi(pf);
            ag += f2lo(pg) + f2hi(pg);
            ao += f2lo(po) + f2hi(po);
        }

        float iv = 1.f / (1.f + expf(-ai));
        float fv = 1.f / (1.f + expf(-af));
        float gv = tanhf(ag);
        float ov = 1.f / (1.f + expf(-ao));
        c = fv * c + iv * gv;
        float h = ov * tanhf(c);

        if (LAYER == 0) {
            g_out0 [(size_t)t * cB * cH + (size_t)b * cH + n] = h;
            g_out0T[((size_t)t * cH + n) * cB + b] = h;          // GEMM1 A layout
        } else {
            g_h1[(size_t)((t + 1) & 1) * cB * cH + (size_t)b * cH + n] = h;
        }

        // grid barrier (monotonic generation)
        __syncthreads();
        if (tid == 0) {
            __threadfence();
            unsigned arr = atomicAdd(&g_bar_count, 1u) + 1u;
            unsigned target = gen + 1u;
            if (arr == (unsigned)NB_REC * target) {
                atomicExch(&g_bar_gen, target);
            } else {
                while (*((volatile unsigned*)&g_bar_gen) < target) { }
            }
            __threadfence();
        }
        gen++;
        __syncthreads();
    }
}

// ----------------------------------------------------------------------------
// Final FC on last h of layer 1 (lives in g_h1 buffer 0: (511+1)&1 == 0)
// ----------------------------------------------------------------------------
__global__ __launch_bounds__(128) void fc_kernel(const float* __restrict__ Wfc,
                                                 const float* __restrict__ bfc,
                                                 float* __restrict__ out)
{
    int b   = blockIdx.x;
    int tid = threadIdx.x;
    const float* h = g_h1 + (size_t)b * cH;
    float s = 0.f;
    for (int k = tid; k < cH; k += 128) s += h[k] * Wfc[k];
    __shared__ float red[128];
    red[tid] = s;
    __syncthreads();
    for (int o = 64; o > 0; o >>= 1) {
        if (tid < o) red[tid] += red[tid + o];
        __syncthreads();
    }
    if (tid == 0) out[b] = red[0] + bfc[0];
}

// ----------------------------------------------------------------------------
extern "C" void kernel_launch(void* const* d_in, const int* in_sizes, int n_in,
                              void* d_out, int out_size)
{
    const float* x     = (const float*)d_in[0];
    const float* W_ih0 = (const float*)d_in[1];
    const float* W_hh0 = (const float*)d_in[2];
    const float* b_ih0 = (const float*)d_in[3];
    const float* b_hh0 = (const float*)d_in[4];
    const float* W_ih1 = (const float*)d_in[5];
    const float* W_hh1 = (const float*)d_in[6];
    const float* b_ih1 = (const float*)d_in[7];
    const float* b_hh1 = (const float*)d_in[8];
    const float* W_fc  = (const float*)d_in[9];
    const float* b_fc  = (const float*)d_in[10];
    float* out = (float*)d_out;
    (void)in_sizes; (void)n_in; (void)out_size;

    cudaFuncSetAttribute(lstm_rec_kernel<0>,
                         cudaFuncAttributeMaxDynamicSharedMemorySize, REC_SMEM);
    cudaFuncSetAttribute(lstm_rec_kernel<1>,
                         cudaFuncAttributeMaxDynamicSharedMemorySize, REC_SMEM);
    cudaFuncSetAttribute(gemm_xg_kernel<0>,
                         cudaFuncAttributeMaxDynamicSharedMemorySize, GEMM_SMEM);
    cudaFuncSetAttribute(gemm_xg_kernel<1>,
                         cudaFuncAttributeMaxDynamicSharedMemorySize, GEMM_SMEM);

    // prep: transpose x, pack input-projection weights
    transpose_x_kernel<<<cT, 256>>>(x);
    pack_w_kernel<0><<<cIN, 256>>>(W_ih0);
    pack_w_kernel<1><<<cH, 256>>>(W_ih1);

    dim3 ggrid(cG / 64, cT);
    gemm_xg_kernel<0><<<ggrid, 256, GEMM_SMEM>>>(b_ih0, b_hh0);
    init_bar_kernel<<<1, 1>>>();
    lstm_rec_kernel<0><<<NB_REC, 256, REC_SMEM>>>(W_hh0);
    gemm_xg_kernel<1><<<ggrid, 256, GEMM_SMEM>>>(b_ih1, b_hh1);
    init_bar_kernel<<<1, 1>>>();
    lstm_rec_kernel<1><<<NB_REC, 256, REC_SMEM>>>(W_hh1);
    fc_kernel<<<cB, 128>>>(W_fc, b_fc, out);
}